// round 3
// baseline (speedup 1.0000x reference)
#include <cuda_runtime.h>
#include <math.h>

// ---------------- scratch (device globals; no allocation) ----------------
__device__ float g_e1[64 * 256 * 256];
__device__ float g_p1[64 * 128 * 128];
__device__ float g_e2[128 * 128 * 128];
__device__ float g_p2[128 * 64 * 64];
__device__ float g_bm[256 * 64 * 64];
__device__ float g_seq[4096 * 256];
__device__ float g_ln[4096 * 256];
__device__ float g_qk[4096 * 256];
__device__ float g_k[4096 * 256];
__device__ float g_v[4096 * 256];
__device__ float g_attno[4096 * 256];
__device__ float g_hdn[4096 * 1024];
__device__ int   g_buckets[4 * 4096];
__device__ int   g_perm[4 * 4096];
__device__ float g_bq[4 * 4096 * 64];
__device__ float g_bk[4 * 4096 * 64];
__device__ float g_bv[4 * 4096 * 64];
__device__ float g_d1[128 * 128 * 128];
__device__ float g_dec1[128 * 128 * 128];
__device__ float g_d2[64 * 256 * 256];
__device__ float g_dec2[64 * 256 * 256];

// ---------------- conv 3x3, pad 1, optional dual-input (concat) ----------------
// block: 256 threads -> 32x32 output tile, 8 output channels, 2x2 px per thread
__global__ void conv3x3_kernel(const float* __restrict__ in0, int C0,
                               const float* __restrict__ in1, int C1,
                               const float* __restrict__ w, const float* __restrict__ bias,
                               float* __restrict__ out, int H, int W, int Cout, int act) {
    __shared__ float sm[34 * 34];
    __shared__ float ws[8 * 9];
    int tid = threadIdx.x;
    int ty = tid >> 4, tx = tid & 15;
    int x0 = blockIdx.x * 32, y0 = blockIdx.y * 32, co0 = blockIdx.z * 8;
    int Cin = C0 + C1;
    float acc[8][4];
#pragma unroll
    for (int o = 0; o < 8; o++)
#pragma unroll
        for (int p = 0; p < 4; p++) acc[o][p] = 0.f;

    for (int ci = 0; ci < Cin; ci++) {
        const float* src = (ci < C0) ? (in0 + (size_t)ci * H * W)
                                     : (in1 + (size_t)(ci - C0) * H * W);
        for (int i = tid; i < 34 * 34; i += 256) {
            int r = i / 34, c = i % 34;
            int gy = y0 - 1 + r, gx = x0 - 1 + c;
            sm[i] = (gy >= 0 && gy < H && gx >= 0 && gx < W) ? src[(size_t)gy * W + gx] : 0.f;
        }
        if (tid < 72) {
            int o = tid / 9, k = tid % 9;
            ws[tid] = (co0 + o < Cout) ? w[((size_t)(co0 + o) * Cin + ci) * 9 + k] : 0.f;
        }
        __syncthreads();

        float win[4][4];
#pragma unroll
        for (int r = 0; r < 4; r++)
#pragma unroll
            for (int c = 0; c < 4; c++) win[r][c] = sm[(2 * ty + r) * 34 + 2 * tx + c];

#pragma unroll
        for (int o = 0; o < 8; o++) {
#pragma unroll
            for (int k = 0; k < 9; k++) {
                float wv = ws[o * 9 + k];
                int ky = k / 3, kx = k % 3;
                acc[o][0] += wv * win[ky][kx];
                acc[o][1] += wv * win[ky][kx + 1];
                acc[o][2] += wv * win[ky + 1][kx];
                acc[o][3] += wv * win[ky + 1][kx + 1];
            }
        }
        __syncthreads();
    }

#pragma unroll
    for (int o = 0; o < 8; o++) {
        int co = co0 + o;
        if (co >= Cout) break;
        float bv = bias[co];
#pragma unroll
        for (int p = 0; p < 4; p++) {
            int y = y0 + 2 * ty + (p >> 1), x = x0 + 2 * tx + (p & 1);
            float v = acc[o][p] + bv;
            if (act == 1) v = fmaxf(v, 0.f);
            else if (act == 2) v = 1.f / (1.f + expf(-v));
            out[((size_t)co * H + y) * W + x] = v;
        }
    }
}

// ---------------- ConvTranspose2d k=4, s=2, p=1 ----------------
// block: 256 threads -> 64x32 output tile, 8 output channels, 4x2 px per thread
__global__ void convT_kernel(const float* __restrict__ in, int Cin,
                             const float* __restrict__ w, const float* __restrict__ bias,
                             float* __restrict__ out, int Hin, int Win, int Cout) {
    __shared__ float sm[34 * 18];
    __shared__ float ws[8 * 16];
    int tid = threadIdx.x;
    int ty = tid >> 4, tx = tid & 15;
    int Hout = 2 * Hin, Wout = 2 * Win;
    int x0 = blockIdx.x * 32, y0 = blockIdx.y * 64, co0 = blockIdx.z * 8;
    int iy0 = y0 / 2 - 1, ix0 = x0 / 2 - 1;
    float acc[8][8];
#pragma unroll
    for (int o = 0; o < 8; o++)
#pragma unroll
        for (int p = 0; p < 8; p++) acc[o][p] = 0.f;

    for (int ci = 0; ci < Cin; ci++) {
        const float* src = in + (size_t)ci * Hin * Win;
        for (int i = tid; i < 34 * 18; i += 256) {
            int r = i / 18, c = i % 18;
            int gy = iy0 + r, gx = ix0 + c;
            sm[i] = (gy >= 0 && gy < Hin && gx >= 0 && gx < Win) ? src[(size_t)gy * Win + gx] : 0.f;
        }
        if (tid < 128) {
            int o = tid >> 4, k = tid & 15;
            ws[tid] = (co0 + o < Cout) ? w[((size_t)ci * Cout + co0 + o) * 16 + k] : 0.f;
        }
        __syncthreads();

        // inputs needed by this thread: rows 2ty..2ty+3, cols tx..tx+2 (smem coords)
        float inv[4][3];
#pragma unroll
        for (int r = 0; r < 4; r++)
#pragma unroll
            for (int c = 0; c < 3; c++) inv[r][c] = sm[(2 * ty + r) * 18 + tx + c];

#pragma unroll
        for (int o = 0; o < 8; o++) {
            float wr[16];
#pragma unroll
            for (int k = 0; k < 16; k++) wr[k] = ws[o * 16 + k];
#pragma unroll
            for (int dy = 0; dy < 4; dy++) {
                int pky = (dy + 1) & 1;           // valid ky parity
                int rbase = (dy + 1 - pky) / 2 + 1; // = row offset base (+1 for pad)
#pragma unroll
                for (int dx = 0; dx < 2; dx++) {
                    int pkx = (dx + 1) & 1;
                    int cbase = (dx + 1 - pkx) / 2 + 1;
                    float a = 0.f;
#pragma unroll
                    for (int kyi = 0; kyi < 2; kyi++) {
                        int ky = pky + 2 * kyi;
                        int rr = rbase - kyi; // 0..3
#pragma unroll
                        for (int kxi = 0; kxi < 2; kxi++) {
                            int kx = pkx + 2 * kxi;
                            int cc = cbase - kxi; // 0..2
                            a += wr[ky * 4 + kx] * inv[rr][cc];
                        }
                    }
                    acc[o][dy * 2 + dx] += a;
                }
            }
        }
        __syncthreads();
    }

#pragma unroll
    for (int o = 0; o < 8; o++) {
        int co = co0 + o;
        if (co >= Cout) break;
        float bv = bias[co];
#pragma unroll
        for (int dy = 0; dy < 4; dy++)
#pragma unroll
            for (int dx = 0; dx < 2; dx++) {
                int y = y0 + 4 * ty + dy, x = x0 + 2 * tx + dx;
                out[((size_t)co * Hout + y) * Wout + x] = acc[o][dy * 2 + dx] + bv;
            }
    }
}

// ---------------- maxpool 2x2 ----------------
__global__ void maxpool_kernel(const float* __restrict__ in, float* __restrict__ out,
                               int C, int H, int W) {
    int idx = blockIdx.x * 256 + threadIdx.x;
    int Ho = H / 2, Wo = W / 2;
    int tot = C * Ho * Wo;
    if (idx >= tot) return;
    int x = idx % Wo, y = (idx / Wo) % Ho, c = idx / (Wo * Ho);
    const float* p = in + ((size_t)c * H + 2 * y) * W + 2 * x;
    out[idx] = fmaxf(fmaxf(p[0], p[1]), fmaxf(p[W], p[W + 1]));
}

// ---------------- NCHW <-> (N=HW, D=C) transposes ----------------
__global__ void seq_from_bm_kernel(const float* __restrict__ bm, float* __restrict__ seq) {
    int idx = blockIdx.x * 256 + threadIdx.x; // 4096*256
    int c = idx & 255, n = idx >> 8;
    seq[idx] = bm[c * 4096 + n];
}
__global__ void bm_from_seq_kernel(const float* __restrict__ seq, float* __restrict__ bm) {
    int idx = blockIdx.x * 256 + threadIdx.x;
    int n = idx & 4095, c = idx >> 12;
    bm[idx] = seq[n * 256 + c];
}

// ---------------- LayerNorm over D=256 ----------------
__global__ void ln_kernel(const float* __restrict__ x, const float* __restrict__ g,
                          const float* __restrict__ b, float* __restrict__ y) {
    __shared__ float red[8];
    int n = blockIdx.x, t = threadIdx.x;
    float v = x[(size_t)n * 256 + t];
    float s = v;
#pragma unroll
    for (int o = 16; o > 0; o >>= 1) s += __shfl_xor_sync(0xffffffffu, s, o);
    if ((t & 31) == 0) red[t >> 5] = s;
    __syncthreads();
    float m = 0.f;
#pragma unroll
    for (int i = 0; i < 8; i++) m += red[i];
    m *= (1.f / 256.f);
    float d = v - m;
    float sq = d * d;
#pragma unroll
    for (int o = 16; o > 0; o >>= 1) sq += __shfl_xor_sync(0xffffffffu, sq, o);
    __syncthreads();
    if ((t & 31) == 0) red[t >> 5] = sq;
    __syncthreads();
    float var = 0.f;
#pragma unroll
    for (int i = 0; i < 8; i++) var += red[i];
    var *= (1.f / 256.f);
    y[(size_t)n * 256 + t] = d / sqrtf(var + 1e-5f) * g[t] + b[t];
}

// ---------------- SGEMM: C[M,N] = act(A[M,K] @ B[K,N] + bias (+ C if accum)) ----------------
// block 256, tile 64x64, BK=16, 4x4 microtile
__global__ void sgemm_kernel(const float* __restrict__ A, const float* __restrict__ B,
                             const float* __restrict__ bias, float* __restrict__ C,
                             int M, int N, int K, int act, int accum) {
    __shared__ float As[16][64];
    __shared__ float Bs[16][68];
    int tid = threadIdx.x;
    int tx = tid & 15, ty = tid >> 4;
    int m0 = blockIdx.y * 64, n0 = blockIdx.x * 64;
    int arow = tid >> 2, acol = (tid & 3) * 4;
    int brow = tid >> 4, bcol = (tid & 15) * 4;
    float acc[4][4];
#pragma unroll
    for (int i = 0; i < 4; i++)
#pragma unroll
        for (int j = 0; j < 4; j++) acc[i][j] = 0.f;

    for (int k0 = 0; k0 < K; k0 += 16) {
        float4 av = *reinterpret_cast<const float4*>(A + (size_t)(m0 + arow) * K + k0 + acol);
        As[acol + 0][arow] = av.x; As[acol + 1][arow] = av.y;
        As[acol + 2][arow] = av.z; As[acol + 3][arow] = av.w;
        float4 bv = *reinterpret_cast<const float4*>(B + (size_t)(k0 + brow) * N + n0 + bcol);
        Bs[brow][bcol + 0] = bv.x; Bs[brow][bcol + 1] = bv.y;
        Bs[brow][bcol + 2] = bv.z; Bs[brow][bcol + 3] = bv.w;
        __syncthreads();
#pragma unroll
        for (int kk = 0; kk < 16; kk++) {
            float a0 = As[kk][ty * 4 + 0], a1 = As[kk][ty * 4 + 1];
            float a2 = As[kk][ty * 4 + 2], a3 = As[kk][ty * 4 + 3];
            float b0 = Bs[kk][tx * 4 + 0], b1 = Bs[kk][tx * 4 + 1];
            float b2 = Bs[kk][tx * 4 + 2], b3 = Bs[kk][tx * 4 + 3];
            acc[0][0] += a0 * b0; acc[0][1] += a0 * b1; acc[0][2] += a0 * b2; acc[0][3] += a0 * b3;
            acc[1][0] += a1 * b0; acc[1][1] += a1 * b1; acc[1][2] += a1 * b2; acc[1][3] += a1 * b3;
            acc[2][0] += a2 * b0; acc[2][1] += a2 * b1; acc[2][2] += a2 * b2; acc[2][3] += a2 * b3;
            acc[3][0] += a3 * b0; acc[3][1] += a3 * b1; acc[3][2] += a3 * b2; acc[3][3] += a3 * b3;
        }
        __syncthreads();
    }

#pragma unroll
    for (int i = 0; i < 4; i++) {
        int r = m0 + ty * 4 + i;
#pragma unroll
        for (int j = 0; j < 4; j++) {
            int c = n0 + tx * 4 + j;
            float v = acc[i][j] + bias[c];
            if (accum) v += C[(size_t)r * N + c];
            if (act == 1) { // gelu (tanh approx, jax default)
                v = 0.5f * v * (1.f + tanhf(0.7978845608028654f * (v + 0.044715f * v * v * v)));
            }
            C[(size_t)r * N + c] = v;
        }
    }
}

// ---------------- normalize keys per (n, head) over dh=64 ----------------
__global__ void knorm_kernel(const float* __restrict__ qk, float* __restrict__ k) {
    int n = blockIdx.x;
    int h = threadIdx.x >> 5, l = threadIdx.x & 31;
    const float* q = qk + (size_t)n * 256 + h * 64;
    float a = q[l], b = q[l + 32];
    float ss = a * a + b * b;
#pragma unroll
    for (int o = 16; o > 0; o >>= 1) ss += __shfl_xor_sync(0xffffffffu, ss, o);
    float inv = 1.f / (sqrtf(ss) + 1e-6f);
    float* kk = k + (size_t)n * 256 + h * 64;
    kk[l] = a * inv; kk[l + 32] = b * inv;
}

// ---------------- LSH bucket: argmax over [rot, -rot] (first-index ties) ----------------
__global__ void bucket_kernel(const float* __restrict__ qk, const float* __restrict__ rot,
                              int* __restrict__ buckets) {
    int n = blockIdx.x;
    int h = threadIdx.x >> 5, r = threadIdx.x & 31;
    const float* q = qk + (size_t)n * 256 + h * 64;
    const float* R = rot + (size_t)h * 2048; // (dh=64, 32)
    float acc = 0.f;
#pragma unroll 8
    for (int d = 0; d < 64; d++) acc += q[d] * R[d * 32 + r];
    float val = acc; int idx = r;
    float nv = -acc;
    if (nv > val) { val = nv; idx = r + 32; }
#pragma unroll
    for (int off = 16; off > 0; off >>= 1) {
        float ov = __shfl_down_sync(0xffffffffu, val, off);
        int oi = __shfl_down_sync(0xffffffffu, idx, off);
        if (ov > val || (ov == val && oi < idx)) { val = ov; idx = oi; }
    }
    if (r == 0) buckets[h * 4096 + n] = idx;
}

// ---------------- stable counting sort by bucket (keys = bucket*N + ticker) ----------------
__global__ void sort_kernel(const int* __restrict__ buckets, int* __restrict__ perm) {
    int t = threadIdx.x;       // 256 threads: (head, bucket)
    int h = t >> 6, b = t & 63;
    const int* bh = buckets + h * 4096;
    int off = 0;
#pragma unroll 4
    for (int n = 0; n < 4096; n++) off += (bh[n] < b) ? 1 : 0;
    int* ph = perm + h * 4096;
    for (int n = 0; n < 4096; n++)
        if (bh[n] == b) ph[off++] = n;
}

// ---------------- gather sorted q/k/v into (h, N, dh) ----------------
__global__ void gather_kernel(const float* __restrict__ qk, const float* __restrict__ k,
                              const float* __restrict__ v, const int* __restrict__ perm,
                              float* __restrict__ bq, float* __restrict__ bk,
                              float* __restrict__ bv) {
    int idx = blockIdx.x * 256 + threadIdx.x; // 4*4096*64
    int d = idx & 63, i = (idx >> 6) & 4095, h = idx >> 18;
    int token = perm[h * 4096 + i];
    size_t s = (size_t)token * 256 + h * 64 + d;
    bq[idx] = qk[s]; bk[idx] = k[s]; bv[idx] = v[s];
}

// ---------------- chunked attention with look-one-back ----------------
#define ATTN_SMEM ((4096 + 128 * 65 + 128 * 65 + 64 * 129) * 4)
__global__ void attn_kernel(const float* __restrict__ bq, const float* __restrict__ bk,
                            const float* __restrict__ bv, const int* __restrict__ perm,
                            float* __restrict__ outp) {
    extern __shared__ float smx[];
    float* qs = smx;                 // 64*64
    float* ks = qs + 4096;           // 128 rows * 65
    float* vs = ks + 128 * 65;       // 128 rows * 65
    float* ds = vs + 128 * 65;       // 64 rows * 129
    __shared__ int spos[64];
    __shared__ int kpos[128];
    int c = blockIdx.x, h = blockIdx.y;
    int tid = threadIdx.x;
    int cprev = (c + 63) & 63;
    const float* bqh = bq + (size_t)h * 262144;
    const float* bkh = bk + (size_t)h * 262144;
    const float* bvh = bv + (size_t)h * 262144;

    for (int i = tid; i < 4096; i += 256) qs[i] = bqh[c * 4096 + i];
    for (int i = tid; i < 8192; i += 256) {
        int j = i >> 6, d = i & 63;
        int sc = (j < 64) ? c : cprev;
        int jj = j & 63;
        size_t off = (size_t)sc * 4096 + jj * 64 + d;
        ks[j * 65 + d] = bkh[off];
        vs[j * 65 + d] = bvh[off];
    }
    if (tid < 64) spos[tid] = perm[h * 4096 + c * 64 + tid];
    else if (tid < 192) {
        int j = tid - 64;
        int sc = (j < 64) ? c : cprev;
        kpos[j] = perm[h * 4096 + sc * 64 + (j & 63)];
    }
    __syncthreads();

    { // dots: 4 rows x 8 cols per thread (cols strided by 16 for bank-freedom)
        int rg = tid >> 4, cg = tid & 15;
        int r0 = rg * 4;
        float acc[4][8];
#pragma unroll
        for (int r = 0; r < 4; r++)
#pragma unroll
            for (int j = 0; j < 8; j++) acc[r][j] = 0.f;
        for (int d = 0; d < 64; d++) {
            float a[4];
#pragma unroll
            for (int r = 0; r < 4; r++) a[r] = qs[(r0 + r) * 64 + d];
#pragma unroll
            for (int j = 0; j < 8; j++) {
                float kv = ks[(cg + 16 * j) * 65 + d];
#pragma unroll
                for (int r = 0; r < 4; r++) acc[r][j] += a[r] * kv;
            }
        }
#pragma unroll
        for (int r = 0; r < 4; r++) {
            int sp = spos[r0 + r];
#pragma unroll
            for (int j = 0; j < 8; j++) {
                int jc = cg + 16 * j;
                float v2 = acc[r][j] * 0.125f;
                if (sp == kpos[jc]) v2 = -1e5f;
                ds[(r0 + r) * 129 + jc] = v2;
            }
        }
    }
    __syncthreads();

    if (tid < 64) { // softmax, one row per thread
        float mx = -1e30f;
        for (int j = 0; j < 128; j++) mx = fmaxf(mx, ds[tid * 129 + j]);
        float s = 0.f;
        for (int j = 0; j < 128; j++) {
            float e = expf(ds[tid * 129 + j] - mx);
            ds[tid * 129 + j] = e; s += e;
        }
        float is = 1.f / s;
        for (int j = 0; j < 128; j++) ds[tid * 129 + j] *= is;
    }
    __syncthreads();

    { // output: 4 rows x 4 dims per thread, scatter through perm (== inv_perm gather)
        int rg = tid >> 4, dg = tid & 15;
        int r0 = rg * 4;
        float acc[4][4];
#pragma unroll
        for (int r = 0; r < 4; r++)
#pragma unroll
            for (int dd = 0; dd < 4; dd++) acc[r][dd] = 0.f;
        for (int j = 0; j < 128; j++) {
            float w4[4];
#pragma unroll
            for (int r = 0; r < 4; r++) w4[r] = ds[(r0 + r) * 129 + j];
#pragma unroll
            for (int dd = 0; dd < 4; dd++) {
                float vv = vs[j * 65 + dg + 16 * dd];
#pragma unroll
                for (int r = 0; r < 4; r++) acc[r][dd] += w4[r] * vv;
            }
        }
#pragma unroll
        for (int r = 0; r < 4; r++) {
            int token = spos[r0 + r];
            float* op = outp + (size_t)token * 256 + h * 64;
#pragma unroll
            for (int dd = 0; dd < 4; dd++) op[dg + 16 * dd] = acc[r][dd];
        }
    }
}

// ---------------- host ----------------
extern "C" void kernel_launch(void* const* d_in, const int* in_sizes, int n_in,
                              void* d_out, int out_size) {
    (void)in_sizes; (void)n_in; (void)out_size;
    const float* burst  = (const float*)d_in[0];
    const float* conv1_w = (const float*)d_in[1];  const float* conv1_b = (const float*)d_in[2];
    const float* conv2_w = (const float*)d_in[3];  const float* conv2_b = (const float*)d_in[4];
    const float* conv3_w = (const float*)d_in[5];  const float* conv3_b = (const float*)d_in[6];
    const float* ln1_g = (const float*)d_in[7];    const float* ln1_b = (const float*)d_in[8];
    const float* Wqk = (const float*)d_in[9];      const float* bqk = (const float*)d_in[10];
    const float* Wv = (const float*)d_in[11];      const float* bvv = (const float*)d_in[12];
    const float* Wo = (const float*)d_in[13];      const float* bo = (const float*)d_in[14];
    const float* rot = (const float*)d_in[15];
    const float* ln2_g = (const float*)d_in[16];   const float* ln2_b = (const float*)d_in[17];
    const float* Wff1 = (const float*)d_in[18];    const float* bff1 = (const float*)d_in[19];
    const float* Wff2 = (const float*)d_in[20];    const float* bff2 = (const float*)d_in[21];
    const float* up1_w = (const float*)d_in[22];   const float* up1_b = (const float*)d_in[23];
    const float* dec1_w = (const float*)d_in[24];  const float* dec1_b = (const float*)d_in[25];
    const float* up2_w = (const float*)d_in[26];   const float* up2_b = (const float*)d_in[27];
    const float* dec2_w = (const float*)d_in[28];  const float* dec2_b = (const float*)d_in[29];
    const float* out_w = (const float*)d_in[30];   const float* out_b = (const float*)d_in[31];
    float* outp = (float*)d_out;

    cudaFuncSetAttribute(attn_kernel, cudaFuncAttributeMaxDynamicSharedMemorySize, ATTN_SMEM);

    float *e1, *p1, *e2, *p2, *bm, *seq, *ln, *qk, *kb, *vb, *attno, *hdn;
    float *bq, *bk, *bv, *d1, *dec1o, *d2, *dec2o;
    int *buckets, *perm;
    cudaGetSymbolAddress((void**)&e1, g_e1);
    cudaGetSymbolAddress((void**)&p1, g_p1);
    cudaGetSymbolAddress((void**)&e2, g_e2);
    cudaGetSymbolAddress((void**)&p2, g_p2);
    cudaGetSymbolAddress((void**)&bm, g_bm);
    cudaGetSymbolAddress((void**)&seq, g_seq);
    cudaGetSymbolAddress((void**)&ln, g_ln);
    cudaGetSymbolAddress((void**)&qk, g_qk);
    cudaGetSymbolAddress((void**)&kb, g_k);
    cudaGetSymbolAddress((void**)&vb, g_v);
    cudaGetSymbolAddress((void**)&attno, g_attno);
    cudaGetSymbolAddress((void**)&hdn, g_hdn);
    cudaGetSymbolAddress((void**)&buckets, g_buckets);
    cudaGetSymbolAddress((void**)&perm, g_perm);
    cudaGetSymbolAddress((void**)&bq, g_bq);
    cudaGetSymbolAddress((void**)&bk, g_bk);
    cudaGetSymbolAddress((void**)&bv, g_bv);
    cudaGetSymbolAddress((void**)&d1, g_d1);
    cudaGetSymbolAddress((void**)&dec1o, g_dec1);
    cudaGetSymbolAddress((void**)&d2, g_d2);
    cudaGetSymbolAddress((void**)&dec2o, g_dec2);

    // ---- encoder (frame 0 only: output keeps only [:, 0]) ----
    conv3x3_kernel<<<dim3(8, 8, 8), 256>>>(burst, 3, nullptr, 0, conv1_w, conv1_b, e1, 256, 256, 64, 1);
    maxpool_kernel<<<(64 * 128 * 128 + 255) / 256, 256>>>(e1, p1, 64, 256, 256);
    conv3x3_kernel<<<dim3(4, 4, 16), 256>>>(p1, 64, nullptr, 0, conv2_w, conv2_b, e2, 128, 128, 128, 1);
    maxpool_kernel<<<(128 * 64 * 64 + 255) / 256, 256>>>(e2, p2, 128, 128, 128);
    conv3x3_kernel<<<dim3(2, 2, 32), 256>>>(p2, 128, nullptr, 0, conv3_w, conv3_b, bm, 64, 64, 256, 1);
    seq_from_bm_kernel<<<4096, 256>>>(bm, seq);

    // ---- reformer: 4 layers ----
    for (int L = 0; L < 4; L++) {
        ln_kernel<<<4096, 256>>>(seq, ln1_g + L * 256, ln1_b + L * 256, ln);
        sgemm_kernel<<<dim3(4, 64), 256>>>(ln, Wqk + (size_t)L * 65536, bqk + L * 256, qk, 4096, 256, 256, 0, 0);
        sgemm_kernel<<<dim3(4, 64), 256>>>(ln, Wv + (size_t)L * 65536, bvv + L * 256, vb, 4096, 256, 256, 0, 0);
        knorm_kernel<<<4096, 128>>>(qk, kb);
        bucket_kernel<<<4096, 128>>>(qk, rot + (size_t)L * 8192, buckets);
        sort_kernel<<<1, 256>>>(buckets, perm);
        gather_kernel<<<4096, 256>>>(qk, kb, vb, perm, bq, bk, bv);
        attn_kernel<<<dim3(64, 4), 256, ATTN_SMEM>>>(bq, bk, bv, perm, attno);
        sgemm_kernel<<<dim3(4, 64), 256>>>(attno, Wo + (size_t)L * 65536, bo + L * 256, seq, 4096, 256, 256, 0, 1);
        ln_kernel<<<4096, 256>>>(seq, ln2_g + L * 256, ln2_b + L * 256, ln);
        sgemm_kernel<<<dim3(16, 64), 256>>>(ln, Wff1 + (size_t)L * 262144, bff1 + L * 1024, hdn, 4096, 1024, 256, 1, 0);
        sgemm_kernel<<<dim3(4, 64), 256>>>(hdn, Wff2 + (size_t)L * 262144, bff2 + L * 256, seq, 4096, 256, 1024, 0, 1);
    }

    bm_from_seq_kernel<<<4096, 256>>>(seq, bm);

    // ---- decoder ----
    convT_kernel<<<dim3(4, 2, 16), 256>>>(bm, 256, up1_w, up1_b, d1, 64, 64, 128);
    conv3x3_kernel<<<dim3(4, 4, 16), 256>>>(d1, 128, e2, 128, dec1_w, dec1_b, dec1o, 128, 128, 128, 1);
    convT_kernel<<<dim3(8, 4, 8), 256>>>(dec1o, 128, up2_w, up2_b, d2, 128, 128, 64);
    conv3x3_kernel<<<dim3(8, 8, 8), 256>>>(d2, 64, e1, 64, dec2_w, dec2_b, dec2o, 256, 256, 64, 1);
    conv3x3_kernel<<<dim3(8, 8, 1), 256>>>(dec2o, 64, nullptr, 0, out_w, out_b, outp, 256, 256, 3, 2);
}

// round 4
// speedup vs baseline: 1.2096x; 1.2096x over previous
#include <cuda_runtime.h>
#include <math.h>

// ---------------- scratch (device globals; no allocation) ----------------
__device__ float g_e1[64 * 256 * 256];
__device__ float g_p1[64 * 128 * 128];
__device__ float g_e2[128 * 128 * 128];
__device__ float g_p2[128 * 64 * 64];
__device__ float g_bm[256 * 64 * 64];
__device__ float g_seq[4096 * 256];
__device__ float g_ln[4096 * 256];
__device__ float g_qk[4096 * 256];
__device__ float g_k[4096 * 256];
__device__ float g_v[4096 * 256];
__device__ float g_attno[4096 * 256];
__device__ float g_hdn[4096 * 1024];
__device__ int   g_buckets[4 * 4096];
__device__ int   g_perm[4 * 4096];
__device__ float g_bq[4 * 4096 * 64];
__device__ float g_bk[4 * 4096 * 64];
__device__ float g_bv[4 * 4096 * 64];
__device__ float g_d1[128 * 128 * 128];
__device__ float g_dec1[128 * 128 * 128];
__device__ float g_d2[64 * 256 * 256];
__device__ float g_dec2[64 * 256 * 256];

// ---------------- conv 3x3, pad 1, dual-input (concat), 64x32 tile ----------------
// 256 threads, each thread: 2 rows x 4 cols of output, CO output channels per block
template<int CO>
__global__ void conv3x3_big(const float* __restrict__ in0, int C0,
                            const float* __restrict__ in1, int C1,
                            const float* __restrict__ w, const float* __restrict__ bias,
                            float* __restrict__ out, int H, int W, int Cout, int act) {
    __shared__ float sm[34 * 66];
    __shared__ float ws[CO * 9];
    int tid = threadIdx.x;
    int tx = tid & 15, ty = tid >> 4;
    int x0 = blockIdx.x * 64, y0 = blockIdx.y * 32, co0 = blockIdx.z * CO;
    int Cin = C0 + C1;
    float acc[CO][8];
#pragma unroll
    for (int o = 0; o < CO; o++)
#pragma unroll
        for (int p = 0; p < 8; p++) acc[o][p] = 0.f;

    for (int ci = 0; ci < Cin; ci++) {
        const float* src = (ci < C0) ? (in0 + (size_t)ci * H * W)
                                     : (in1 + (size_t)(ci - C0) * H * W);
        for (int i = tid; i < 34 * 66; i += 256) {
            int r = i / 66, c = i % 66;
            int gy = y0 - 1 + r, gx = x0 - 1 + c;
            sm[i] = (gy >= 0 && gy < H && gx >= 0 && gx < W) ? src[(size_t)gy * W + gx] : 0.f;
        }
        if (tid < CO * 9) {
            int o = tid / 9, k = tid % 9;
            ws[tid] = (co0 + o < Cout) ? w[((size_t)(co0 + o) * Cin + ci) * 9 + k] : 0.f;
        }
        __syncthreads();

        float win[4][6];
#pragma unroll
        for (int r = 0; r < 4; r++)
#pragma unroll
            for (int c = 0; c < 6; c++) win[r][c] = sm[(2 * ty + r) * 66 + 4 * tx + c];

#pragma unroll
        for (int o = 0; o < CO; o++) {
#pragma unroll
            for (int ky = 0; ky < 3; ky++)
#pragma unroll
                for (int kx = 0; kx < 3; kx++) {
                    float wv = ws[o * 9 + ky * 3 + kx];
#pragma unroll
                    for (int py = 0; py < 2; py++)
#pragma unroll
                        for (int px = 0; px < 4; px++)
                            acc[o][py * 4 + px] += wv * win[py + ky][px + kx];
                }
        }
        __syncthreads();
    }

#pragma unroll
    for (int o = 0; o < CO; o++) {
        int co = co0 + o;
        if (co >= Cout) break;
        float bv = bias[co];
#pragma unroll
        for (int py = 0; py < 2; py++) {
            float4 v;
            float t0 = acc[o][py * 4 + 0] + bv, t1 = acc[o][py * 4 + 1] + bv;
            float t2 = acc[o][py * 4 + 2] + bv, t3 = acc[o][py * 4 + 3] + bv;
            if (act == 1) {
                t0 = fmaxf(t0, 0.f); t1 = fmaxf(t1, 0.f);
                t2 = fmaxf(t2, 0.f); t3 = fmaxf(t3, 0.f);
            } else if (act == 2) {
                t0 = 1.f / (1.f + expf(-t0)); t1 = 1.f / (1.f + expf(-t1));
                t2 = 1.f / (1.f + expf(-t2)); t3 = 1.f / (1.f + expf(-t3));
            }
            v.x = t0; v.y = t1; v.z = t2; v.w = t3;
            *reinterpret_cast<float4*>(out + ((size_t)co * H + y0 + 2 * ty + py) * W + x0 + 4 * tx) = v;
        }
    }
}

// ---------------- ConvTranspose2d k=4, s=2, p=1; 64x64 out tile, 4 co, 4x4 px ----------------
__global__ void convT_big(const float* __restrict__ in, int Cin,
                          const float* __restrict__ w, const float* __restrict__ bias,
                          float* __restrict__ out, int Hin, int Win, int Cout) {
    __shared__ float sm[34 * 34];
    __shared__ float ws[4 * 16];
    int tid = threadIdx.x;
    int tx = tid & 15, ty = tid >> 4;
    int Hout = 2 * Hin, Wout = 2 * Win;
    int x0 = blockIdx.x * 64, y0 = blockIdx.y * 64, co0 = blockIdx.z * 4;
    int iy0 = y0 / 2 - 1, ix0 = x0 / 2 - 1;
    float acc[4][16];
#pragma unroll
    for (int o = 0; o < 4; o++)
#pragma unroll
        for (int p = 0; p < 16; p++) acc[o][p] = 0.f;

    for (int ci = 0; ci < Cin; ci++) {
        const float* src = in + (size_t)ci * Hin * Win;
        for (int i = tid; i < 34 * 34; i += 256) {
            int r = i / 34, c = i % 34;
            int gy = iy0 + r, gx = ix0 + c;
            sm[i] = (gy >= 0 && gy < Hin && gx >= 0 && gx < Win) ? src[(size_t)gy * Win + gx] : 0.f;
        }
        if (tid < 64)
            ws[tid] = w[((size_t)ci * Cout + co0 + (tid >> 4)) * 16 + (tid & 15)];
        __syncthreads();

        float inv[4][4];
#pragma unroll
        for (int r = 0; r < 4; r++)
#pragma unroll
            for (int c = 0; c < 4; c++) inv[r][c] = sm[(2 * ty + r) * 34 + 2 * tx + c];

#pragma unroll
        for (int o = 0; o < 4; o++) {
#pragma unroll
            for (int dy = 0; dy < 4; dy++) {
                int pky = (dy + 1) & 1;
#pragma unroll
                for (int dx = 0; dx < 4; dx++) {
                    int pkx = (dx + 1) & 1;
                    float a = 0.f;
#pragma unroll
                    for (int kyi = 0; kyi < 2; kyi++) {
                        int ky = pky + 2 * kyi;
                        int rr = (dy + 1 - ky) / 2 + 1;
#pragma unroll
                        for (int kxi = 0; kxi < 2; kxi++) {
                            int kx = pkx + 2 * kxi;
                            int cc = (dx + 1 - kx) / 2 + 1;
                            a += ws[o * 16 + ky * 4 + kx] * inv[rr][cc];
                        }
                    }
                    acc[o][dy * 4 + dx] += a;
                }
            }
        }
        __syncthreads();
    }

#pragma unroll
    for (int o = 0; o < 4; o++) {
        int co = co0 + o;
        float bv = bias[co];
#pragma unroll
        for (int dy = 0; dy < 4; dy++) {
            float4 v;
            v.x = acc[o][dy * 4 + 0] + bv; v.y = acc[o][dy * 4 + 1] + bv;
            v.z = acc[o][dy * 4 + 2] + bv; v.w = acc[o][dy * 4 + 3] + bv;
            *reinterpret_cast<float4*>(out + ((size_t)co * Hout + y0 + 4 * ty + dy) * Wout + x0 + 4 * tx) = v;
        }
    }
}

// ---------------- maxpool 2x2 ----------------
__global__ void maxpool_kernel(const float* __restrict__ in, float* __restrict__ out,
                               int C, int H, int W) {
    int idx = blockIdx.x * 256 + threadIdx.x;
    int Ho = H / 2, Wo = W / 2;
    int tot = C * Ho * Wo;
    if (idx >= tot) return;
    int x = idx % Wo, y = (idx / Wo) % Ho, c = idx / (Wo * Ho);
    const float* p = in + ((size_t)c * H + 2 * y) * W + 2 * x;
    out[idx] = fmaxf(fmaxf(p[0], p[1]), fmaxf(p[W], p[W + 1]));
}

// ---------------- NCHW <-> (N=HW, D=C) transposes ----------------
__global__ void seq_from_bm_kernel(const float* __restrict__ bm, float* __restrict__ seq) {
    int idx = blockIdx.x * 256 + threadIdx.x; // 4096*256
    int c = idx & 255, n = idx >> 8;
    seq[idx] = bm[c * 4096 + n];
}
__global__ void bm_from_seq_kernel(const float* __restrict__ seq, float* __restrict__ bm) {
    int idx = blockIdx.x * 256 + threadIdx.x;
    int n = idx & 4095, c = idx >> 12;
    bm[idx] = seq[n * 256 + c];
}

// ---------------- LayerNorm over D=256 ----------------
__global__ void ln_kernel(const float* __restrict__ x, const float* __restrict__ g,
                          const float* __restrict__ b, float* __restrict__ y) {
    __shared__ float red[8];
    int n = blockIdx.x, t = threadIdx.x;
    float v = x[(size_t)n * 256 + t];
    float s = v;
#pragma unroll
    for (int o = 16; o > 0; o >>= 1) s += __shfl_xor_sync(0xffffffffu, s, o);
    if ((t & 31) == 0) red[t >> 5] = s;
    __syncthreads();
    float m = 0.f;
#pragma unroll
    for (int i = 0; i < 8; i++) m += red[i];
    m *= (1.f / 256.f);
    float d = v - m;
    float sq = d * d;
#pragma unroll
    for (int o = 16; o > 0; o >>= 1) sq += __shfl_xor_sync(0xffffffffu, sq, o);
    __syncthreads();
    if ((t & 31) == 0) red[t >> 5] = sq;
    __syncthreads();
    float var = 0.f;
#pragma unroll
    for (int i = 0; i < 8; i++) var += red[i];
    var *= (1.f / 256.f);
    y[(size_t)n * 256 + t] = d / sqrtf(var + 1e-5f) * g[t] + b[t];
}

// ---------------- SGEMM: 128xBN tile, 8x(BN/16) microtile, BK=16 ----------------
template<int BN>
__global__ void sgemm_big(const float* __restrict__ A, const float* __restrict__ B,
                          const float* __restrict__ bias, float* __restrict__ C,
                          int M, int N, int K, int act, int accum) {
    constexpr int TN = BN / 16;
    __shared__ float As[16][128];
    __shared__ float Bs[16][BN];
    int tid = threadIdx.x;
    int tx = tid & 15, ty = tid >> 4;
    int m0 = blockIdx.y * 128, n0 = blockIdx.x * BN;
    int a_r = tid >> 1, a_c = (tid & 1) * 8;
    int b_r = tid >> 4;
    int b_c = (BN == 128) ? (tid & 15) * 8 : (tid & 15) * 4;
    float acc[8][TN];
#pragma unroll
    for (int i = 0; i < 8; i++)
#pragma unroll
        for (int j = 0; j < TN; j++) acc[i][j] = 0.f;

    for (int k0 = 0; k0 < K; k0 += 16) {
        const float* Ap = A + (size_t)(m0 + a_r) * K + k0 + a_c;
        float4 av0 = *reinterpret_cast<const float4*>(Ap);
        float4 av1 = *reinterpret_cast<const float4*>(Ap + 4);
        As[a_c + 0][a_r] = av0.x; As[a_c + 1][a_r] = av0.y;
        As[a_c + 2][a_r] = av0.z; As[a_c + 3][a_r] = av0.w;
        As[a_c + 4][a_r] = av1.x; As[a_c + 5][a_r] = av1.y;
        As[a_c + 6][a_r] = av1.z; As[a_c + 7][a_r] = av1.w;
        const float* Bp = B + (size_t)(k0 + b_r) * N + n0 + b_c;
        if (BN == 128) {
            *reinterpret_cast<float4*>(&Bs[b_r][b_c]) = *reinterpret_cast<const float4*>(Bp);
            *reinterpret_cast<float4*>(&Bs[b_r][b_c + 4]) = *reinterpret_cast<const float4*>(Bp + 4);
        } else {
            *reinterpret_cast<float4*>(&Bs[b_r][b_c]) = *reinterpret_cast<const float4*>(Bp);
        }
        __syncthreads();
#pragma unroll
        for (int kk = 0; kk < 16; kk++) {
            float a[8], b[TN];
            *reinterpret_cast<float4*>(&a[0]) = *reinterpret_cast<float4*>(&As[kk][ty * 8]);
            *reinterpret_cast<float4*>(&a[4]) = *reinterpret_cast<float4*>(&As[kk][ty * 8 + 4]);
#pragma unroll
            for (int j4 = 0; j4 < TN / 4; j4++)
                *reinterpret_cast<float4*>(&b[j4 * 4]) = *reinterpret_cast<float4*>(&Bs[kk][tx * TN + j4 * 4]);
#pragma unroll
            for (int i = 0; i < 8; i++)
#pragma unroll
                for (int j = 0; j < TN; j++) acc[i][j] += a[i] * b[j];
        }
        __syncthreads();
    }

#pragma unroll
    for (int i = 0; i < 8; i++) {
        int r = m0 + ty * 8 + i;
        float* Crow = C + (size_t)r * N + n0 + tx * TN;
        const float* brow = bias + n0 + tx * TN;
#pragma unroll
        for (int j4 = 0; j4 < TN / 4; j4++) {
            float4 bv = *reinterpret_cast<const float4*>(brow + j4 * 4);
            float v0 = acc[i][j4 * 4 + 0] + bv.x;
            float v1 = acc[i][j4 * 4 + 1] + bv.y;
            float v2 = acc[i][j4 * 4 + 2] + bv.z;
            float v3 = acc[i][j4 * 4 + 3] + bv.w;
            if (accum) {
                float4 cv = *reinterpret_cast<const float4*>(Crow + j4 * 4);
                v0 += cv.x; v1 += cv.y; v2 += cv.z; v3 += cv.w;
            }
            if (act == 1) {
                v0 = 0.5f * v0 * (1.f + tanhf(0.7978845608028654f * (v0 + 0.044715f * v0 * v0 * v0)));
                v1 = 0.5f * v1 * (1.f + tanhf(0.7978845608028654f * (v1 + 0.044715f * v1 * v1 * v1)));
                v2 = 0.5f * v2 * (1.f + tanhf(0.7978845608028654f * (v2 + 0.044715f * v2 * v2 * v2)));
                v3 = 0.5f * v3 * (1.f + tanhf(0.7978845608028654f * (v3 + 0.044715f * v3 * v3 * v3)));
            }
            float4 ov; ov.x = v0; ov.y = v1; ov.z = v2; ov.w = v3;
            *reinterpret_cast<float4*>(Crow + j4 * 4) = ov;
        }
    }
}

// ---------------- normalize keys per (n, head) over dh=64 ----------------
__global__ void knorm_kernel(const float* __restrict__ qk, float* __restrict__ k) {
    int n = blockIdx.x;
    int h = threadIdx.x >> 5, l = threadIdx.x & 31;
    const float* q = qk + (size_t)n * 256 + h * 64;
    float a = q[l], b = q[l + 32];
    float ss = a * a + b * b;
#pragma unroll
    for (int o = 16; o > 0; o >>= 1) ss += __shfl_xor_sync(0xffffffffu, ss, o);
    float inv = 1.f / (sqrtf(ss) + 1e-6f);
    float* kk = k + (size_t)n * 256 + h * 64;
    kk[l] = a * inv; kk[l + 32] = b * inv;
}

// ---------------- LSH bucket: argmax over [rot, -rot] (first-index ties) ----------------
__global__ void bucket_kernel(const float* __restrict__ qk, const float* __restrict__ rot,
                              int* __restrict__ buckets) {
    int n = blockIdx.x;
    int h = threadIdx.x >> 5, r = threadIdx.x & 31;
    const float* q = qk + (size_t)n * 256 + h * 64;
    const float* R = rot + (size_t)h * 2048; // (dh=64, 32)
    float acc = 0.f;
#pragma unroll 8
    for (int d = 0; d < 64; d++) acc += q[d] * R[d * 32 + r];
    float val = acc; int idx = r;
    float nv = -acc;
    if (nv > val) { val = nv; idx = r + 32; }
#pragma unroll
    for (int off = 16; off > 0; off >>= 1) {
        float ov = __shfl_down_sync(0xffffffffu, val, off);
        int oi = __shfl_down_sync(0xffffffffu, idx, off);
        if (ov > val || (ov == val && oi < idx)) { val = ov; idx = oi; }
    }
    if (r == 0) buckets[h * 4096 + n] = idx;
}

// ---------------- stable counting sort (chunked, parallel), one block per head ----------------
__global__ void sort_kernel(const int* __restrict__ buckets, int* __restrict__ perm) {
    __shared__ unsigned short cnt[64][257];
    __shared__ int base[64];
    int h = blockIdx.x, t = threadIdx.x;
    const int* bh = buckets + h * 4096;
#pragma unroll
    for (int b = 0; b < 64; b++) cnt[b][t] = 0;
    __syncthreads();
    int myb[16];
#pragma unroll
    for (int i = 0; i < 16; i++) myb[i] = bh[t * 16 + i];
#pragma unroll
    for (int i = 0; i < 16; i++) cnt[myb[i]][t]++;
    __syncthreads();
    if (t < 64) {
        int running = 0;
        for (int c = 0; c < 256; c++) {
            int v = cnt[t][c];
            cnt[t][c] = (unsigned short)running;
            running += v;
        }
        base[t] = running; // total for bucket t
    }
    __syncthreads();
    if (t == 0) {
        int running = 0;
        for (int b = 0; b < 64; b++) { int v = base[b]; base[b] = running; running += v; }
    }
    __syncthreads();
    int* ph = perm + h * 4096;
#pragma unroll
    for (int i = 0; i < 16; i++) {
        int b = myb[i];
        int pos = base[b] + cnt[b][t];
        cnt[b][t]++;
        ph[pos] = t * 16 + i;
    }
}

// ---------------- gather sorted q/k/v into (h, N, dh) ----------------
__global__ void gather_kernel(const float* __restrict__ qk, const float* __restrict__ k,
                              const float* __restrict__ v, const int* __restrict__ perm,
                              float* __restrict__ bq, float* __restrict__ bk,
                              float* __restrict__ bv) {
    int idx = blockIdx.x * 256 + threadIdx.x; // 4*4096*64
    int d = idx & 63, i = (idx >> 6) & 4095, h = idx >> 18;
    int token = perm[h * 4096 + i];
    size_t s = (size_t)token * 256 + h * 64 + d;
    bq[idx] = qk[s]; bk[idx] = k[s]; bv[idx] = v[s];
}

// ---------------- chunked attention with look-one-back ----------------
#define ATTN_SMEM ((4096 + 128 * 65 + 128 * 65 + 64 * 129) * 4)
__global__ void attn_kernel(const float* __restrict__ bq, const float* __restrict__ bk,
                            const float* __restrict__ bv, const int* __restrict__ perm,
                            float* __restrict__ outp) {
    extern __shared__ float smx[];
    float* qs = smx;                 // 64*64
    float* ks = qs + 4096;           // 128 rows * 65
    float* vs = ks + 128 * 65;       // 128 rows * 65
    float* ds = vs + 128 * 65;       // 64 rows * 129
    __shared__ int spos[64];
    __shared__ int kpos[128];
    int c = blockIdx.x, h = blockIdx.y;
    int tid = threadIdx.x;
    int cprev = (c + 63) & 63;
    const float* bqh = bq + (size_t)h * 262144;
    const float* bkh = bk + (size_t)h * 262144;
    const float* bvh = bv + (size_t)h * 262144;

    for (int i = tid; i < 4096; i += 256) qs[i] = bqh[c * 4096 + i];
    for (int i = tid; i < 8192; i += 256) {
        int j = i >> 6, d = i & 63;
        int sc = (j < 64) ? c : cprev;
        int jj = j & 63;
        size_t off = (size_t)sc * 4096 + jj * 64 + d;
        ks[j * 65 + d] = bkh[off];
        vs[j * 65 + d] = bvh[off];
    }
    if (tid < 64) spos[tid] = perm[h * 4096 + c * 64 + tid];
    else if (tid < 192) {
        int j = tid - 64;
        int sc = (j < 64) ? c : cprev;
        kpos[j] = perm[h * 4096 + sc * 64 + (j & 63)];
    }
    __syncthreads();

    { // dots
        int rg = tid >> 4, cg = tid & 15;
        int r0 = rg * 4;
        float acc[4][8];
#pragma unroll
        for (int r = 0; r < 4; r++)
#pragma unroll
            for (int j = 0; j < 8; j++) acc[r][j] = 0.f;
        for (int d = 0; d < 64; d++) {
            float a[4];
#pragma unroll
            for (int r = 0; r < 4; r++) a[r] = qs[(r0 + r) * 64 + d];
#pragma unroll
            for (int j = 0; j < 8; j++) {
                float kv = ks[(cg + 16 * j) * 65 + d];
#pragma unroll
                for (int r = 0; r < 4; r++) acc[r][j] += a[r] * kv;
            }
        }
#pragma unroll
        for (int r = 0; r < 4; r++) {
            int sp = spos[r0 + r];
#pragma unroll
            for (int j = 0; j < 8; j++) {
                int jc = cg + 16 * j;
                float v2 = acc[r][j] * 0.125f;
                if (sp == kpos[jc]) v2 = -1e5f;
                ds[(r0 + r) * 129 + jc] = v2;
            }
        }
    }
    __syncthreads();

    if (tid < 64) { // softmax
        float mx = -1e30f;
        for (int j = 0; j < 128; j++) mx = fmaxf(mx, ds[tid * 129 + j]);
        float s = 0.f;
        for (int j = 0; j < 128; j++) {
            float e = expf(ds[tid * 129 + j] - mx);
            ds[tid * 129 + j] = e; s += e;
        }
        float is = 1.f / s;
        for (int j = 0; j < 128; j++) ds[tid * 129 + j] *= is;
    }
    __syncthreads();

    { // output, scatter through perm
        int rg = tid >> 4, dg = tid & 15;
        int r0 = rg * 4;
        float acc[4][4];
#pragma unroll
        for (int r = 0; r < 4; r++)
#pragma unroll
            for (int dd = 0; dd < 4; dd++) acc[r][dd] = 0.f;
        for (int j = 0; j < 128; j++) {
            float w4[4];
#pragma unroll
            for (int r = 0; r < 4; r++) w4[r] = ds[(r0 + r) * 129 + j];
#pragma unroll
            for (int dd = 0; dd < 4; dd++) {
                float vv = vs[j * 65 + dg + 16 * dd];
#pragma unroll
                for (int r = 0; r < 4; r++) acc[r][dd] += w4[r] * vv;
            }
        }
#pragma unroll
        for (int r = 0; r < 4; r++) {
            int token = spos[r0 + r];
            float* op = outp + (size_t)token * 256 + h * 64;
#pragma unroll
            for (int dd = 0; dd < 4; dd++) op[dg + 16 * dd] = acc[r][dd];
        }
    }
}

// ---------------- host ----------------
extern "C" void kernel_launch(void* const* d_in, const int* in_sizes, int n_in,
                              void* d_out, int out_size) {
    (void)in_sizes; (void)n_in; (void)out_size;
    const float* burst  = (const float*)d_in[0];
    const float* conv1_w = (const float*)d_in[1];  const float* conv1_b = (const float*)d_in[2];
    const float* conv2_w = (const float*)d_in[3];  const float* conv2_b = (const float*)d_in[4];
    const float* conv3_w = (const float*)d_in[5];  const float* conv3_b = (const float*)d_in[6];
    const float* ln1_g = (const float*)d_in[7];    const float* ln1_b = (const float*)d_in[8];
    const float* Wqk = (const float*)d_in[9];      const float* bqk = (const float*)d_in[10];
    const float* Wv = (const float*)d_in[11];      const float* bvv = (const float*)d_in[12];
    const float* Wo = (const float*)d_in[13];      const float* bo = (const float*)d_in[14];
    const float* rot = (const float*)d_in[15];
    const float* ln2_g = (const float*)d_in[16];   const float* ln2_b = (const float*)d_in[17];
    const float* Wff1 = (const float*)d_in[18];    const float* bff1 = (const float*)d_in[19];
    const float* Wff2 = (const float*)d_in[20];    const float* bff2 = (const float*)d_in[21];
    const float* up1_w = (const float*)d_in[22];   const float* up1_b = (const float*)d_in[23];
    const float* dec1_w = (const float*)d_in[24];  const float* dec1_b = (const float*)d_in[25];
    const float* up2_w = (const float*)d_in[26];   const float* up2_b = (const float*)d_in[27];
    const float* dec2_w = (const float*)d_in[28];  const float* dec2_b = (const float*)d_in[29];
    const float* out_w = (const float*)d_in[30];   const float* out_b = (const float*)d_in[31];
    float* outp = (float*)d_out;

    cudaFuncSetAttribute(attn_kernel, cudaFuncAttributeMaxDynamicSharedMemorySize, ATTN_SMEM);

    float *e1, *p1, *e2, *p2, *bm, *seq, *ln, *qk, *kb, *vb, *attno, *hdn;
    float *bq, *bk, *bv, *d1, *dec1o, *d2, *dec2o;
    int *buckets, *perm;
    cudaGetSymbolAddress((void**)&e1, g_e1);
    cudaGetSymbolAddress((void**)&p1, g_p1);
    cudaGetSymbolAddress((void**)&e2, g_e2);
    cudaGetSymbolAddress((void**)&p2, g_p2);
    cudaGetSymbolAddress((void**)&bm, g_bm);
    cudaGetSymbolAddress((void**)&seq, g_seq);
    cudaGetSymbolAddress((void**)&ln, g_ln);
    cudaGetSymbolAddress((void**)&qk, g_qk);
    cudaGetSymbolAddress((void**)&kb, g_k);
    cudaGetSymbolAddress((void**)&vb, g_v);
    cudaGetSymbolAddress((void**)&attno, g_attno);
    cudaGetSymbolAddress((void**)&hdn, g_hdn);
    cudaGetSymbolAddress((void**)&buckets, g_buckets);
    cudaGetSymbolAddress((void**)&perm, g_perm);
    cudaGetSymbolAddress((void**)&bq, g_bq);
    cudaGetSymbolAddress((void**)&bk, g_bk);
    cudaGetSymbolAddress((void**)&bv, g_bv);
    cudaGetSymbolAddress((void**)&d1, g_d1);
    cudaGetSymbolAddress((void**)&dec1o, g_dec1);
    cudaGetSymbolAddress((void**)&d2, g_d2);
    cudaGetSymbolAddress((void**)&dec2o, g_dec2);

    // ---- encoder (frame 0 only: output keeps only [:, 0]) ----
    conv3x3_big<8><<<dim3(4, 8, 8), 256>>>(burst, 3, nullptr, 0, conv1_w, conv1_b, e1, 256, 256, 64, 1);
    maxpool_kernel<<<(64 * 128 * 128 + 255) / 256, 256>>>(e1, p1, 64, 256, 256);
    conv3x3_big<8><<<dim3(2, 4, 16), 256>>>(p1, 64, nullptr, 0, conv2_w, conv2_b, e2, 128, 128, 128, 1);
    maxpool_kernel<<<(128 * 64 * 64 + 255) / 256, 256>>>(e2, p2, 128, 128, 128);
    conv3x3_big<4><<<dim3(1, 2, 64), 256>>>(p2, 128, nullptr, 0, conv3_w, conv3_b, bm, 64, 64, 256, 1);
    seq_from_bm_kernel<<<4096, 256>>>(bm, seq);

    // ---- reformer: 4 layers ----
    for (int L = 0; L < 4; L++) {
        ln_kernel<<<4096, 256>>>(seq, ln1_g + L * 256, ln1_b + L * 256, ln);
        sgemm_big<64><<<dim3(4, 32), 256>>>(ln, Wqk + (size_t)L * 65536, bqk + L * 256, qk, 4096, 256, 256, 0, 0);
        sgemm_big<64><<<dim3(4, 32), 256>>>(ln, Wv + (size_t)L * 65536, bvv + L * 256, vb, 4096, 256, 256, 0, 0);
        knorm_kernel<<<4096, 128>>>(qk, kb);
        bucket_kernel<<<4096, 128>>>(qk, rot + (size_t)L * 8192, buckets);
        sort_kernel<<<4, 256>>>(buckets, perm);
        gather_kernel<<<4096, 256>>>(qk, kb, vb, perm, bq, bk, bv);
        attn_kernel<<<dim3(64, 4), 256, ATTN_SMEM>>>(bq, bk, bv, perm, attno);
        sgemm_big<64><<<dim3(4, 32), 256>>>(attno, Wo + (size_t)L * 65536, bo + L * 256, seq, 4096, 256, 256, 0, 1);
        ln_kernel<<<4096, 256>>>(seq, ln2_g + L * 256, ln2_b + L * 256, ln);
        sgemm_big<128><<<dim3(8, 32), 256>>>(ln, Wff1 + (size_t)L * 262144, bff1 + L * 1024, hdn, 4096, 1024, 256, 1, 0);
        sgemm_big<64><<<dim3(4, 32), 256>>>(hdn, Wff2 + (size_t)L * 262144, bff2 + L * 256, seq, 4096, 256, 1024, 0, 1);
    }

    bm_from_seq_kernel<<<4096, 256>>>(seq, bm);

    // ---- decoder ----
    convT_big<<<dim3(2, 2, 32), 256>>>(bm, 256, up1_w, up1_b, d1, 64, 64, 128);
    conv3x3_big<8><<<dim3(2, 4, 16), 256>>>(d1, 128, e2, 128, dec1_w, dec1_b, dec1o, 128, 128, 128, 1);
    convT_big<<<dim3(4, 4, 16), 256>>>(dec1o, 128, up2_w, up2_b, d2, 128, 128, 64);
    conv3x3_big<8><<<dim3(4, 8, 8), 256>>>(d2, 64, e1, 64, dec2_w, dec2_b, dec2o, 256, 256, 64, 1);
    conv3x3_big<4><<<dim3(4, 8, 1), 256>>>(dec2o, 64, nullptr, 0, out_w, out_b, outp, 256, 256, 3, 2);
}

// round 8
// speedup vs baseline: 1.2587x; 1.0405x over previous
#include <cuda_runtime.h>
#include <math.h>

// ---------------- scratch (device globals; no allocation) ----------------
__device__ float g_e1[64 * 256 * 256];
__device__ float g_p1[64 * 128 * 128];
__device__ float g_e2[128 * 128 * 128];
__device__ float g_p2[128 * 64 * 64];
__device__ float g_bm[256 * 64 * 64];
__device__ float g_seq[4096 * 256];
__device__ float g_ln[4096 * 256];
__device__ float g_qk[4096 * 256];
__device__ float g_k[4096 * 256];
__device__ float g_v[4096 * 256];
__device__ float g_attno[4096 * 256];
__device__ float g_hdn[4096 * 1024];
__device__ int   g_buckets[4 * 4096];
__device__ int   g_perm[4 * 4096];
__device__ float g_bq[4 * 4096 * 64];
__device__ float g_bk[4 * 4096 * 64];
__device__ float g_bv[4 * 4096 * 64];
__device__ float g_d1[128 * 128 * 128];
__device__ float g_dec1[128 * 128 * 128];
__device__ float g_d2[64 * 256 * 256];
__device__ float g_dec2[64 * 256 * 256];

// ---------------- conv 3x3, pad 1, dual-input (concat), 64x32 tile ----------------
template<int CO>
__global__ void conv3x3_big(const float* __restrict__ in0, int C0,
                            const float* __restrict__ in1, int C1,
                            const float* __restrict__ w, const float* __restrict__ bias,
                            float* __restrict__ out, int H, int W, int Cout, int act) {
    __shared__ float sm[34 * 66];
    __shared__ float ws[CO * 9];
    int tid = threadIdx.x;
    int tx = tid & 15, ty = tid >> 4;
    int x0 = blockIdx.x * 64, y0 = blockIdx.y * 32, co0 = blockIdx.z * CO;
    int Cin = C0 + C1;
    float acc[CO][8];
#pragma unroll
    for (int o = 0; o < CO; o++)
#pragma unroll
        for (int p = 0; p < 8; p++) acc[o][p] = 0.f;

    for (int ci = 0; ci < Cin; ci++) {
        const float* src = (ci < C0) ? (in0 + (size_t)ci * H * W)
                                     : (in1 + (size_t)(ci - C0) * H * W);
        for (int i = tid; i < 34 * 66; i += 256) {
            int r = i / 66, c = i % 66;
            int gy = y0 - 1 + r, gx = x0 - 1 + c;
            sm[i] = (gy >= 0 && gy < H && gx >= 0 && gx < W) ? src[(size_t)gy * W + gx] : 0.f;
        }
        if (tid < CO * 9) {
            int o = tid / 9, k = tid % 9;
            ws[tid] = (co0 + o < Cout) ? w[((size_t)(co0 + o) * Cin + ci) * 9 + k] : 0.f;
        }
        __syncthreads();

        float win[4][6];
#pragma unroll
        for (int r = 0; r < 4; r++)
#pragma unroll
            for (int c = 0; c < 6; c++) win[r][c] = sm[(2 * ty + r) * 66 + 4 * tx + c];

#pragma unroll
        for (int o = 0; o < CO; o++) {
#pragma unroll
            for (int ky = 0; ky < 3; ky++)
#pragma unroll
                for (int kx = 0; kx < 3; kx++) {
                    float wv = ws[o * 9 + ky * 3 + kx];
#pragma unroll
                    for (int py = 0; py < 2; py++)
#pragma unroll
                        for (int px = 0; px < 4; px++)
                            acc[o][py * 4 + px] += wv * win[py + ky][px + kx];
                }
        }
        __syncthreads();
    }

#pragma unroll
    for (int o = 0; o < CO; o++) {
        int co = co0 + o;
        if (co >= Cout) break;
        float bv = bias[co];
#pragma unroll
        for (int py = 0; py < 2; py++) {
            float4 v;
            float t0 = acc[o][py * 4 + 0] + bv, t1 = acc[o][py * 4 + 1] + bv;
            float t2 = acc[o][py * 4 + 2] + bv, t3 = acc[o][py * 4 + 3] + bv;
            if (act == 1) {
                t0 = fmaxf(t0, 0.f); t1 = fmaxf(t1, 0.f);
                t2 = fmaxf(t2, 0.f); t3 = fmaxf(t3, 0.f);
            } else if (act == 2) {
                t0 = 1.f / (1.f + expf(-t0)); t1 = 1.f / (1.f + expf(-t1));
                t2 = 1.f / (1.f + expf(-t2)); t3 = 1.f / (1.f + expf(-t3));
            }
            v.x = t0; v.y = t1; v.z = t2; v.w = t3;
            *reinterpret_cast<float4*>(out + ((size_t)co * H + y0 + 2 * ty + py) * W + x0 + 4 * tx) = v;
        }
    }
}

// ---------------- ConvTranspose2d k=4, s=2, p=1; 64x64 out tile, 4 co, 4x4 px ----------------
__global__ void convT_big(const float* __restrict__ in, int Cin,
                          const float* __restrict__ w, const float* __restrict__ bias,
                          float* __restrict__ out, int Hin, int Win, int Cout) {
    __shared__ float sm[34 * 34];
    __shared__ float ws[4 * 16];
    int tid = threadIdx.x;
    int tx = tid & 15, ty = tid >> 4;
    int Hout = 2 * Hin, Wout = 2 * Win;
    int x0 = blockIdx.x * 64, y0 = blockIdx.y * 64, co0 = blockIdx.z * 4;
    int iy0 = y0 / 2 - 1, ix0 = x0 / 2 - 1;
    float acc[4][16];
#pragma unroll
    for (int o = 0; o < 4; o++)
#pragma unroll
        for (int p = 0; p < 16; p++) acc[o][p] = 0.f;

    for (int ci = 0; ci < Cin; ci++) {
        const float* src = in + (size_t)ci * Hin * Win;
        for (int i = tid; i < 34 * 34; i += 256) {
            int r = i / 34, c = i % 34;
            int gy = iy0 + r, gx = ix0 + c;
            sm[i] = (gy >= 0 && gy < Hin && gx >= 0 && gx < Win) ? src[(size_t)gy * Win + gx] : 0.f;
        }
        if (tid < 64)
            ws[tid] = w[((size_t)ci * Cout + co0 + (tid >> 4)) * 16 + (tid & 15)];
        __syncthreads();

        float inv[4][4];
#pragma unroll
        for (int r = 0; r < 4; r++)
#pragma unroll
            for (int c = 0; c < 4; c++) inv[r][c] = sm[(2 * ty + r) * 34 + 2 * tx + c];

#pragma unroll
        for (int o = 0; o < 4; o++) {
#pragma unroll
            for (int dy = 0; dy < 4; dy++) {
                int pky = (dy + 1) & 1;
#pragma unroll
                for (int dx = 0; dx < 4; dx++) {
                    int pkx = (dx + 1) & 1;
                    float a = 0.f;
#pragma unroll
                    for (int kyi = 0; kyi < 2; kyi++) {
                        int ky = pky + 2 * kyi;
                        int rr = (dy + 1 - ky) / 2 + 1;
#pragma unroll
                        for (int kxi = 0; kxi < 2; kxi++) {
                            int kx = pkx + 2 * kxi;
                            int cc = (dx + 1 - kx) / 2 + 1;
                            a += ws[o * 16 + ky * 4 + kx] * inv[rr][cc];
                        }
                    }
                    acc[o][dy * 4 + dx] += a;
                }
            }
        }
        __syncthreads();
    }

#pragma unroll
    for (int o = 0; o < 4; o++) {
        int co = co0 + o;
        float bv = bias[co];
#pragma unroll
        for (int dy = 0; dy < 4; dy++) {
            float4 v;
            v.x = acc[o][dy * 4 + 0] + bv; v.y = acc[o][dy * 4 + 1] + bv;
            v.z = acc[o][dy * 4 + 2] + bv; v.w = acc[o][dy * 4 + 3] + bv;
            *reinterpret_cast<float4*>(out + ((size_t)co * Hout + y0 + 4 * ty + dy) * Wout + x0 + 4 * tx) = v;
        }
    }
}

// ---------------- maxpool 2x2 ----------------
__global__ void maxpool_kernel(const float* __restrict__ in, float* __restrict__ out,
                               int C, int H, int W) {
    int idx = blockIdx.x * 256 + threadIdx.x;
    int Ho = H / 2, Wo = W / 2;
    int tot = C * Ho * Wo;
    if (idx >= tot) return;
    int x = idx % Wo, y = (idx / Wo) % Ho, c = idx / (Wo * Ho);
    const float* p = in + ((size_t)c * H + 2 * y) * W + 2 * x;
    out[idx] = fmaxf(fmaxf(p[0], p[1]), fmaxf(p[W], p[W + 1]));
}

// ---------------- NCHW <-> (N=HW, D=C) transposes ----------------
__global__ void seq_from_bm_kernel(const float* __restrict__ bm, float* __restrict__ seq) {
    int idx = blockIdx.x * 256 + threadIdx.x; // 4096*256
    int c = idx & 255, n = idx >> 8;
    seq[idx] = bm[c * 4096 + n];
}
__global__ void bm_from_seq_kernel(const float* __restrict__ seq, float* __restrict__ bm) {
    int idx = blockIdx.x * 256 + threadIdx.x;
    int n = idx & 4095, c = idx >> 12;
    bm[idx] = seq[n * 256 + c];
}

// ---------------- LayerNorm over D=256 ----------------
__global__ void ln_kernel(const float* __restrict__ x, const float* __restrict__ g,
                          const float* __restrict__ b, float* __restrict__ y) {
    __shared__ float red[8];
    int n = blockIdx.x, t = threadIdx.x;
    float v = x[(size_t)n * 256 + t];
    float s = v;
#pragma unroll
    for (int o = 16; o > 0; o >>= 1) s += __shfl_xor_sync(0xffffffffu, s, o);
    if ((t & 31) == 0) red[t >> 5] = s;
    __syncthreads();
    float m = 0.f;
#pragma unroll
    for (int i = 0; i < 8; i++) m += red[i];
    m *= (1.f / 256.f);
    float d = v - m;
    float sq = d * d;
#pragma unroll
    for (int o = 16; o > 0; o >>= 1) sq += __shfl_xor_sync(0xffffffffu, sq, o);
    __syncthreads();
    if ((t & 31) == 0) red[t >> 5] = sq;
    __syncthreads();
    float var = 0.f;
#pragma unroll
    for (int i = 0; i < 8; i++) var += red[i];
    var *= (1.f / 256.f);
    y[(size_t)n * 256 + t] = d / sqrtf(var + 1e-5f) * g[t] + b[t];
}

// ---------------- 3xTF32 tensor-core GEMM (fp32-class accuracy) ----------------
// C = act(A@B + bias (+C)); A[M,K] row, B[K,N] row. 128xBN tile, m16n8k8,
// operands split x = hi + lo (hi = tf32(x)), D = Ah*Bh + Ah*Bl + Al*Bh.
__device__ __forceinline__ unsigned f2tf32(float x) {
    unsigned r;
    asm("cvt.rna.tf32.f32 %0, %1;" : "=r"(r) : "f"(x));
    return r;
}

template<int BN>
__global__ void mma_gemm3(const float* __restrict__ A, const float* __restrict__ B,
                          const float* __restrict__ bias, float* __restrict__ C,
                          int M, int N, int K, int act, int accum) {
    constexpr int NT = BN / 16;        // n-tiles (of 8) per warp
    constexpr int AST = 136;           // stride mod 32 == 8 -> conflict-free frags
    constexpr int BST = BN + 8;
    extern __shared__ unsigned smu[];
    unsigned* AsH = smu;               // [32][AST] k-major
    unsigned* AsL = AsH + 32 * AST;
    unsigned* BsH = AsL + 32 * AST;    // [32][BST]
    unsigned* BsL = BsH + 32 * BST;

    int tid = threadIdx.x;
    int warp = tid >> 5, lane = tid & 31;
    int g = lane >> 2, tq = lane & 3;
    int warp_m = warp >> 1, warp_n = warp & 1;
    int m0 = blockIdx.y * 128, n0 = blockIdx.x * BN;

    float acc[2][NT][4];
#pragma unroll
    for (int mi = 0; mi < 2; mi++)
#pragma unroll
        for (int ni = 0; ni < NT; ni++)
#pragma unroll
            for (int q = 0; q < 4; q++) acc[mi][ni][q] = 0.f;

    int ar = tid >> 1, akq = (tid & 1) * 16;       // A: 128 rows x 32 k
    int bk = tid >> 3, bnq = (tid & 7) * (BN / 8); // B: 32 k x BN

    for (int k0 = 0; k0 < K; k0 += 32) {
        const float* Ap = A + (size_t)(m0 + ar) * K + k0 + akq;
#pragma unroll
        for (int i = 0; i < 4; i++) {
            float4 v = *reinterpret_cast<const float4*>(Ap + 4 * i);
            float xs[4] = {v.x, v.y, v.z, v.w};
#pragma unroll
            for (int j = 0; j < 4; j++) {
                unsigned h = f2tf32(xs[j]);
                float lo = xs[j] - __uint_as_float(h);
                AsH[(akq + 4 * i + j) * AST + ar] = h;
                AsL[(akq + 4 * i + j) * AST + ar] = f2tf32(lo);
            }
        }
        const float* Bp = B + (size_t)(k0 + bk) * N + n0 + bnq;
#pragma unroll
        for (int i = 0; i < BN / 32; i++) {
            float4 v = *reinterpret_cast<const float4*>(Bp + 4 * i);
            float xs[4] = {v.x, v.y, v.z, v.w};
#pragma unroll
            for (int j = 0; j < 4; j++) {
                unsigned h = f2tf32(xs[j]);
                float lo = xs[j] - __uint_as_float(h);
                BsH[bk * BST + bnq + 4 * i + j] = h;
                BsL[bk * BST + bnq + 4 * i + j] = f2tf32(lo);
            }
        }
        __syncthreads();

#pragma unroll
        for (int ks = 0; ks < 32; ks += 8) {
            unsigned aH[2][4], aL[2][4], bH[NT][2], bL[NT][2];
#pragma unroll
            for (int mi = 0; mi < 2; mi++) {
                int mb = warp_m * 32 + mi * 16;
                aH[mi][0] = AsH[(ks + tq) * AST + mb + g];
                aH[mi][1] = AsH[(ks + tq) * AST + mb + g + 8];
                aH[mi][2] = AsH[(ks + tq + 4) * AST + mb + g];
                aH[mi][3] = AsH[(ks + tq + 4) * AST + mb + g + 8];
                aL[mi][0] = AsL[(ks + tq) * AST + mb + g];
                aL[mi][1] = AsL[(ks + tq) * AST + mb + g + 8];
                aL[mi][2] = AsL[(ks + tq + 4) * AST + mb + g];
                aL[mi][3] = AsL[(ks + tq + 4) * AST + mb + g + 8];
            }
#pragma unroll
            for (int ni = 0; ni < NT; ni++) {
                int nb = warp_n * (BN / 2) + ni * 8;
                bH[ni][0] = BsH[(ks + tq) * BST + nb + g];
                bH[ni][1] = BsH[(ks + tq + 4) * BST + nb + g];
                bL[ni][0] = BsL[(ks + tq) * BST + nb + g];
                bL[ni][1] = BsL[(ks + tq + 4) * BST + nb + g];
            }
#pragma unroll
            for (int mi = 0; mi < 2; mi++)
#pragma unroll
                for (int ni = 0; ni < NT; ni++) {
                    asm volatile(
                        "mma.sync.aligned.m16n8k8.row.col.f32.tf32.tf32.f32 "
                        "{%0,%1,%2,%3}, {%4,%5,%6,%7}, {%8,%9}, {%0,%1,%2,%3};\n"
                        : "+f"(acc[mi][ni][0]), "+f"(acc[mi][ni][1]),
                          "+f"(acc[mi][ni][2]), "+f"(acc[mi][ni][3])
                        : "r"(aH[mi][0]), "r"(aH[mi][1]), "r"(aH[mi][2]), "r"(aH[mi][3]),
                          "r"(bH[ni][0]), "r"(bH[ni][1]));
                    asm volatile(
                        "mma.sync.aligned.m16n8k8.row.col.f32.tf32.tf32.f32 "
                        "{%0,%1,%2,%3}, {%4,%5,%6,%7}, {%8,%9}, {%0,%1,%2,%3};\n"
                        : "+f"(acc[mi][ni][0]), "+f"(acc[mi][ni][1]),
                          "+f"(acc[mi][ni][2]), "+f"(acc[mi][ni][3])
                        : "r"(aH[mi][0]), "r"(aH[mi][1]), "r"(aH[mi][2]), "r"(aH[mi][3]),
                          "r"(bL[ni][0]), "r"(bL[ni][1]));
                    asm volatile(
                        "mma.sync.aligned.m16n8k8.row.col.f32.tf32.tf32.f32 "
                        "{%0,%1,%2,%3}, {%4,%5,%6,%7}, {%8,%9}, {%0,%1,%2,%3};\n"
                        : "+f"(acc[mi][ni][0]), "+f"(acc[mi][ni][1]),
                          "+f"(acc[mi][ni][2]), "+f"(acc[mi][ni][3])
                        : "r"(aL[mi][0]), "r"(aL[mi][1]), "r"(aL[mi][2]), "r"(aL[mi][3]),
                          "r"(bH[ni][0]), "r"(bH[ni][1]));
                }
        }
        __syncthreads();
    }

    int row_base = m0 + warp_m * 32 + g;
    int col_base = n0 + warp_n * (BN / 2) + 2 * tq;
#pragma unroll
    for (int mi = 0; mi < 2; mi++) {
#pragma unroll
        for (int ni = 0; ni < NT; ni++) {
            int col = col_base + ni * 8;
            float bv0 = bias[col], bv1 = bias[col + 1];
#pragma unroll
            for (int half = 0; half < 2; half++) {
                int row = row_base + mi * 16 + half * 8;
                float v0 = acc[mi][ni][half * 2 + 0] + bv0;
                float v1 = acc[mi][ni][half * 2 + 1] + bv1;
                float* Cp = C + (size_t)row * N + col;
                if (accum) {
                    float2 cv = *reinterpret_cast<const float2*>(Cp);
                    v0 += cv.x; v1 += cv.y;
                }
                if (act == 1) {
                    v0 = 0.5f * v0 * (1.f + tanhf(0.7978845608028654f * (v0 + 0.044715f * v0 * v0 * v0)));
                    v1 = 0.5f * v1 * (1.f + tanhf(0.7978845608028654f * (v1 + 0.044715f * v1 * v1 * v1)));
                }
                float2 ov; ov.x = v0; ov.y = v1;
                *reinterpret_cast<float2*>(Cp) = ov;
            }
        }
    }
}

#define SM3_64  ((2 * 32 * 136 + 2 * 32 * 72) * 4)
#define SM3_128 ((2 * 32 * 136 + 2 * 32 * 136) * 4)

// ---------------- normalize keys per (n, head) over dh=64 ----------------
__global__ void knorm_kernel(const float* __restrict__ qk, float* __restrict__ k) {
    int n = blockIdx.x;
    int h = threadIdx.x >> 5, l = threadIdx.x & 31;
    const float* q = qk + (size_t)n * 256 + h * 64;
    float a = q[l], b = q[l + 32];
    float ss = a * a + b * b;
#pragma unroll
    for (int o = 16; o > 0; o >>= 1) ss += __shfl_xor_sync(0xffffffffu, ss, o);
    float inv = 1.f / (sqrtf(ss) + 1e-6f);
    float* kk = k + (size_t)n * 256 + h * 64;
    kk[l] = a * inv; kk[l + 32] = b * inv;
}

// ---------------- LSH bucket: argmax over [rot, -rot] (first-index ties) ----------------
__global__ void bucket_kernel(const float* __restrict__ qk, const float* __restrict__ rot,
                              int* __restrict__ buckets) {
    int n = blockIdx.x;
    int h = threadIdx.x >> 5, r = threadIdx.x & 31;
    const float* q = qk + (size_t)n * 256 + h * 64;
    const float* R = rot + (size_t)h * 2048; // (dh=64, 32)
    float acc = 0.f;
#pragma unroll 8
    for (int d = 0; d < 64; d++) acc += q[d] * R[d * 32 + r];
    float val = acc; int idx = r;
    float nv = -acc;
    if (nv > val) { val = nv; idx = r + 32; }
#pragma unroll
    for (int off = 16; off > 0; off >>= 1) {
        float ov = __shfl_down_sync(0xffffffffu, val, off);
        int oi = __shfl_down_sync(0xffffffffu, idx, off);
        if (ov > val || (ov == val && oi < idx)) { val = ov; idx = oi; }
    }
    if (r == 0) buckets[h * 4096 + n] = idx;
}

// ---------------- stable counting sort (chunked, parallel), one block per head ----------------
__global__ void sort_kernel(const int* __restrict__ buckets, int* __restrict__ perm) {
    __shared__ unsigned short cnt[64][257];
    __shared__ int base[64];
    int h = blockIdx.x, t = threadIdx.x;
    const int* bh = buckets + h * 4096;
#pragma unroll
    for (int b = 0; b < 64; b++) cnt[b][t] = 0;
    __syncthreads();
    int myb[16];
#pragma unroll
    for (int i = 0; i < 16; i++) myb[i] = bh[t * 16 + i];
#pragma unroll
    for (int i = 0; i < 16; i++) cnt[myb[i]][t]++;
    __syncthreads();
    if (t < 64) {
        int running = 0;
        for (int c = 0; c < 256; c++) {
            int v = cnt[t][c];
            cnt[t][c] = (unsigned short)running;
            running += v;
        }
        base[t] = running;
    }
    __syncthreads();
    if (t == 0) {
        int running = 0;
        for (int b = 0; b < 64; b++) { int v = base[b]; base[b] = running; running += v; }
    }
    __syncthreads();
    int* ph = perm + h * 4096;
#pragma unroll
    for (int i = 0; i < 16; i++) {
        int b = myb[i];
        int pos = base[b] + cnt[b][t];
        cnt[b][t]++;
        ph[pos] = t * 16 + i;
    }
}

// ---------------- gather sorted q/k/v into (h, N, dh) ----------------
__global__ void gather_kernel(const float* __restrict__ qk, const float* __restrict__ k,
                              const float* __restrict__ v, const int* __restrict__ perm,
                              float* __restrict__ bq, float* __restrict__ bk,
                              float* __restrict__ bv) {
    int idx = blockIdx.x * 256 + threadIdx.x; // 4*4096*64
    int d = idx & 63, i = (idx >> 6) & 4095, h = idx >> 18;
    int token = perm[h * 4096 + i];
    size_t s = (size_t)token * 256 + h * 64 + d;
    bq[idx] = qk[s]; bk[idx] = k[s]; bv[idx] = v[s];
}

// ---------------- chunked attention with look-one-back ----------------
#define ATTN_SMEM ((4096 + 128 * 65 + 128 * 65 + 64 * 129) * 4)
__global__ void attn_kernel(const float* __restrict__ bq, const float* __restrict__ bk,
                            const float* __restrict__ bv, const int* __restrict__ perm,
                            float* __restrict__ outp) {
    extern __shared__ float smx[];
    float* qs = smx;                 // 64*64
    float* ks = qs + 4096;           // 128 rows * 65
    float* vs = ks + 128 * 65;       // 128 rows * 65
    float* ds = vs + 128 * 65;       // 64 rows * 129
    __shared__ int spos[64];
    __shared__ int kpos[128];
    int c = blockIdx.x, h = blockIdx.y;
    int tid = threadIdx.x;
    int cprev = (c + 63) & 63;
    const float* bqh = bq + (size_t)h * 262144;
    const float* bkh = bk + (size_t)h * 262144;
    const float* bvh = bv + (size_t)h * 262144;

    for (int i = tid; i < 4096; i += 256) qs[i] = bqh[c * 4096 + i];
    for (int i = tid; i < 8192; i += 256) {
        int j = i >> 6, d = i & 63;
        int sc = (j < 64) ? c : cprev;
        int jj = j & 63;
        size_t off = (size_t)sc * 4096 + jj * 64 + d;
        ks[j * 65 + d] = bkh[off];
        vs[j * 65 + d] = bvh[off];
    }
    if (tid < 64) spos[tid] = perm[h * 4096 + c * 64 + tid];
    else if (tid < 192) {
        int j = tid - 64;
        int sc = (j < 64) ? c : cprev;
        kpos[j] = perm[h * 4096 + sc * 64 + (j & 63)];
    }
    __syncthreads();

    { // dots
        int rg = tid >> 4, cg = tid & 15;
        int r0 = rg * 4;
        float acc[4][8];
#pragma unroll
        for (int r = 0; r < 4; r++)
#pragma unroll
            for (int j = 0; j < 8; j++) acc[r][j] = 0.f;
        for (int d = 0; d < 64; d++) {
            float a[4];
#pragma unroll
            for (int r = 0; r < 4; r++) a[r] = qs[(r0 + r) * 64 + d];
#pragma unroll
            for (int j = 0; j < 8; j++) {
                float kv = ks[(cg + 16 * j) * 65 + d];
#pragma unroll
                for (int r = 0; r < 4; r++) acc[r][j] += a[r] * kv;
            }
        }
#pragma unroll
        for (int r = 0; r < 4; r++) {
            int sp = spos[r0 + r];
#pragma unroll
            for (int j = 0; j < 8; j++) {
                int jc = cg + 16 * j;
                float v2 = acc[r][j] * 0.125f;
                if (sp == kpos[jc]) v2 = -1e5f;
                ds[(r0 + r) * 129 + jc] = v2;
            }
        }
    }
    __syncthreads();

    if (tid < 64) { // softmax
        float mx = -1e30f;
        for (int j = 0; j < 128; j++) mx = fmaxf(mx, ds[tid * 129 + j]);
        float s = 0.f;
        for (int j = 0; j < 128; j++) {
            float e = expf(ds[tid * 129 + j] - mx);
            ds[tid * 129 + j] = e; s += e;
        }
        float is = 1.f / s;
        for (int j = 0; j < 128; j++) ds[tid * 129 + j] *= is;
    }
    __syncthreads();

    { // output, scatter through perm
        int rg = tid >> 4, dg = tid & 15;
        int r0 = rg * 4;
        float acc[4][4];
#pragma unroll
        for (int r = 0; r < 4; r++)
#pragma unroll
            for (int dd = 0; dd < 4; dd++) acc[r][dd] = 0.f;
        for (int j = 0; j < 128; j++) {
            float w4[4];
#pragma unroll
            for (int r = 0; r < 4; r++) w4[r] = ds[(r0 + r) * 129 + j];
#pragma unroll
            for (int dd = 0; dd < 4; dd++) {
                float vv = vs[j * 65 + dg + 16 * dd];
#pragma unroll
                for (int r = 0; r < 4; r++) acc[r][dd] += w4[r] * vv;
            }
        }
#pragma unroll
        for (int r = 0; r < 4; r++) {
            int token = spos[r0 + r];
            float* op = outp + (size_t)token * 256 + h * 64;
#pragma unroll
            for (int dd = 0; dd < 4; dd++) op[dg + 16 * dd] = acc[r][dd];
        }
    }
}

// ---------------- host ----------------
extern "C" void kernel_launch(void* const* d_in, const int* in_sizes, int n_in,
                              void* d_out, int out_size) {
    (void)in_sizes; (void)n_in; (void)out_size;
    const float* burst  = (const float*)d_in[0];
    const float* conv1_w = (const float*)d_in[1];  const float* conv1_b = (const float*)d_in[2];
    const float* conv2_w = (const float*)d_in[3];  const float* conv2_b = (const float*)d_in[4];
    const float* conv3_w = (const float*)d_in[5];  const float* conv3_b = (const float*)d_in[6];
    const float* ln1_g = (const float*)d_in[7];    const float* ln1_b = (const float*)d_in[8];
    const float* Wqk = (const float*)d_in[9];      const float* bqk = (const float*)d_in[10];
    const float* Wv = (const float*)d_in[11];      const float* bvv = (const float*)d_in[12];
    const float* Wo = (const float*)d_in[13];      const float* bo = (const float*)d_in[14];
    const float* rot = (const float*)d_in[15];
    const float* ln2_g = (const float*)d_in[16];   const float* ln2_b = (const float*)d_in[17];
    const float* Wff1 = (const float*)d_in[18];    const float* bff1 = (const float*)d_in[19];
    const float* Wff2 = (const float*)d_in[20];    const float* bff2 = (const float*)d_in[21];
    const float* up1_w = (const float*)d_in[22];   const float* up1_b = (const float*)d_in[23];
    const float* dec1_w = (const float*)d_in[24];  const float* dec1_b = (const float*)d_in[25];
    const float* up2_w = (const float*)d_in[26];   const float* up2_b = (const float*)d_in[27];
    const float* dec2_w = (const float*)d_in[28];  const float* dec2_b = (const float*)d_in[29];
    const float* out_w = (const float*)d_in[30];   const float* out_b = (const float*)d_in[31];
    float* outp = (float*)d_out;

    cudaFuncSetAttribute(attn_kernel, cudaFuncAttributeMaxDynamicSharedMemorySize, ATTN_SMEM);
    cudaFuncSetAttribute(mma_gemm3<64>, cudaFuncAttributeMaxDynamicSharedMemorySize, SM3_64);
    cudaFuncSetAttribute(mma_gemm3<128>, cudaFuncAttributeMaxDynamicSharedMemorySize, SM3_128);

    float *e1, *p1, *e2, *p2, *bm, *seq, *ln, *qk, *kb, *vb, *attno, *hdn;
    float *bq, *bk, *bv, *d1, *dec1o, *d2, *dec2o;
    int *buckets, *perm;
    cudaGetSymbolAddress((void**)&e1, g_e1);
    cudaGetSymbolAddress((void**)&p1, g_p1);
    cudaGetSymbolAddress((void**)&e2, g_e2);
    cudaGetSymbolAddress((void**)&p2, g_p2);
    cudaGetSymbolAddress((void**)&bm, g_bm);
    cudaGetSymbolAddress((void**)&seq, g_seq);
    cudaGetSymbolAddress((void**)&ln, g_ln);
    cudaGetSymbolAddress((void**)&qk, g_qk);
    cudaGetSymbolAddress((void**)&kb, g_k);
    cudaGetSymbolAddress((void**)&vb, g_v);
    cudaGetSymbolAddress((void**)&attno, g_attno);
    cudaGetSymbolAddress((void**)&hdn, g_hdn);
    cudaGetSymbolAddress((void**)&buckets, g_buckets);
    cudaGetSymbolAddress((void**)&perm, g_perm);
    cudaGetSymbolAddress((void**)&bq, g_bq);
    cudaGetSymbolAddress((void**)&bk, g_bk);
    cudaGetSymbolAddress((void**)&bv, g_bv);
    cudaGetSymbolAddress((void**)&d1, g_d1);
    cudaGetSymbolAddress((void**)&dec1o, g_dec1);
    cudaGetSymbolAddress((void**)&d2, g_d2);
    cudaGetSymbolAddress((void**)&dec2o, g_dec2);

    // ---- encoder (frame 0 only: output keeps only [:, 0]) ----
    conv3x3_big<8><<<dim3(4, 8, 8), 256>>>(burst, 3, nullptr, 0, conv1_w, conv1_b, e1, 256, 256, 64, 1);
    maxpool_kernel<<<(64 * 128 * 128 + 255) / 256, 256>>>(e1, p1, 64, 256, 256);
    conv3x3_big<8><<<dim3(2, 4, 16), 256>>>(p1, 64, nullptr, 0, conv2_w, conv2_b, e2, 128, 128, 128, 1);
    maxpool_kernel<<<(128 * 64 * 64 + 255) / 256, 256>>>(e2, p2, 128, 128, 128);
    conv3x3_big<4><<<dim3(1, 2, 64), 256>>>(p2, 128, nullptr, 0, conv3_w, conv3_b, bm, 64, 64, 256, 1);
    seq_from_bm_kernel<<<4096, 256>>>(bm, seq);

    // ---- reformer: 4 layers (all GEMMs 3xTF32 tensor-core) ----
    for (int L = 0; L < 4; L++) {
        ln_kernel<<<4096, 256>>>(seq, ln1_g + L * 256, ln1_b + L * 256, ln);
        mma_gemm3<64><<<dim3(4, 32), 256, SM3_64>>>(ln, Wqk + (size_t)L * 65536, bqk + L * 256, qk, 4096, 256, 256, 0, 0);
        mma_gemm3<64><<<dim3(4, 32), 256, SM3_64>>>(ln, Wv + (size_t)L * 65536, bvv + L * 256, vb, 4096, 256, 256, 0, 0);
        knorm_kernel<<<4096, 128>>>(qk, kb);
        bucket_kernel<<<4096, 128>>>(qk, rot + (size_t)L * 8192, buckets);
        sort_kernel<<<4, 256>>>(buckets, perm);
        gather_kernel<<<4096, 256>>>(qk, kb, vb, perm, bq, bk, bv);
        attn_kernel<<<dim3(64, 4), 256, ATTN_SMEM>>>(bq, bk, bv, perm, attno);
        mma_gemm3<64><<<dim3(4, 32), 256, SM3_64>>>(attno, Wo + (size_t)L * 65536, bo + L * 256, seq, 4096, 256, 256, 0, 1);
        ln_kernel<<<4096, 256>>>(seq, ln2_g + L * 256, ln2_b + L * 256, ln);
        mma_gemm3<128><<<dim3(8, 32), 256, SM3_128>>>(ln, Wff1 + (size_t)L * 262144, bff1 + L * 1024, hdn, 4096, 1024, 256, 1, 0);
        mma_gemm3<64><<<dim3(4, 32), 256, SM3_64>>>(hdn, Wff2 + (size_t)L * 262144, bff2 + L * 256, seq, 4096, 256, 1024, 0, 1);
    }

    bm_from_seq_kernel<<<4096, 256>>>(seq, bm);

    // ---- decoder ----
    convT_big<<<dim3(2, 2, 32), 256>>>(bm, 256, up1_w, up1_b, d1, 64, 64, 128);
    conv3x3_big<8><<<dim3(2, 4, 16), 256>>>(d1, 128, e2, 128, dec1_w, dec1_b, dec1o, 128, 128, 128, 1);
    convT_big<<<dim3(4, 4, 16), 256>>>(dec1o, 128, up2_w, up2_b, d2, 128, 128, 64);
    conv3x3_big<8><<<dim3(4, 8, 8), 256>>>(d2, 64, e1, 64, dec2_w, dec2_b, dec2o, 256, 256, 64, 1);
    conv3x3_big<4><<<dim3(4, 8, 1), 256>>>(dec2o, 64, nullptr, 0, out_w, out_b, outp, 256, 256, 3, 2);
}